// round 13
// baseline (speedup 1.0000x reference)
#include <cuda_runtime.h>
#include <cuda_bf16.h>
#include <cuda_fp16.h>
#include <cstdint>

// Problem dims (fixed by the reference)
#define VOCAB 50000
#define EDIM  64
#define HDIM  64
#define BATCH 1024
#define SEQ   512

// Scratch: projected table proj[v][h] = b_ih[h]+b_hh[h] + sum_e emb[v,e]*W_ih[h,e]
__device__ float g_proj[VOCAB * HDIM];   // 12.8 MB, L2-resident in steady state
__device__ int   g_x64flag;              // 1 if token buffer is int64, 0 if int32

// Fast tanh: tanh(x) = 1 - 2/(1 + exp(2x)). ex2.approx + rcp.approx,
// rel err ~1e-6 (vs ~6e-4 for tanh.approx.f32).
__device__ __forceinline__ float fast_tanh(float x) {
    float e, r;
    asm("ex2.approx.f32 %0, %1;" : "=f"(e) : "f"(x * 2.885390081777927f)); // 2/ln2
    asm("rcp.approx.f32 %0, %1;" : "=f"(r) : "f"(e + 1.0f));
    return fmaf(-2.0f, r, 1.0f);
}

#define FMA2(acc, a, b) asm("fma.rn.f32x2 %0, %1, %2, %0;" : "+l"(acc) : "l"(a), "l"(b))
#define ADD2(acc, b)    asm("add.rn.f32x2 %0, %0, %1;"     : "+l"(acc) : "l"(b))
#define PACK2F(d, lo, hi) asm("mov.b64 %0, {%1, %2};" : "=l"(d) : "f"(lo), "f"(hi))
#define UNPACK2(lo, hi, s) asm("mov.b64 {%0, %1}, %2;" : "=f"(lo), "=f"(hi) : "l"(s))

// Expand a bf16x2 word (h[2l] in lo half, h[2l+1] in hi half) into a packed
// f32x2 operand: lo f32 = v<<16, hi f32 = v & 0xffff0000. Two 4-cyc alu ops
// (SHF+LOP3) -- no F2F converts (the R12 mistake).
__device__ __forceinline__ unsigned long long bf16pair_to_f32x2(uint32_t v) {
    uint32_t lo = v << 16;
    uint32_t hi = v & 0xffff0000u;
    unsigned long long p;
    asm("mov.b64 %0, {%1, %2};" : "=l"(p) : "r"(lo), "r"(hi));
    return p;
}
// Pack two f32 h values into one bf16x2 word (lo = h0, hi = h1), 1 instr.
__device__ __forceinline__ uint32_t f32pair_to_bf16x2(float h0, float h1) {
    uint32_t u;
    asm("cvt.rn.bf16x2.f32 %0, %1, %2;" : "=r"(u) : "f"(h1), "f"(h0));
    return u;
}

// ---------------------------------------------------------------------------
// Kernel A: build projected embedding table (fuses gather-side GEMM + biases).
// Block 0 warp 0 additionally detects int32-vs-int64 token layout: tokens are
// in [0,50000), so for little-endian int64 every odd 32-bit word is 0.
// ---------------------------------------------------------------------------
#define PROJ_ROWS 32
__global__ __launch_bounds__(256) void proj_kernel(
    const int*   __restrict__ x32,
    const float* __restrict__ emb,
    const float* __restrict__ W_ih,
    const float* __restrict__ b_ih,
    const float* __restrict__ b_hh)
{
    __shared__ float s_w[HDIM * 65];
    __shared__ float s_e[PROJ_ROWS * EDIM];
    __shared__ float s_bias[HDIM];

    const int t  = threadIdx.x;
    const int v0 = blockIdx.x * PROJ_ROWS;

    if (blockIdx.x == 0 && t < 32) {
        unsigned m = __ballot_sync(0xffffffff, x32[2 * t + 1] != 0);
        if (t == 0) g_x64flag = (m == 0u) ? 1 : 0;
    }

    #pragma unroll
    for (int k = 0; k < 16; k++) {
        int idx = t + k * 256;                 // 0..4095
        int hg = idx >> 6, eg = idx & 63;
        s_w[hg * 65 + eg] = W_ih[idx];
    }
    #pragma unroll
    for (int k = 0; k < 8; k++) {
        int idx = t + k * 256;                 // 0..2047
        int r = idx >> 6, e = idx & 63;
        s_e[idx] = (v0 + r < VOCAB) ? emb[(long)(v0 + r) * EDIM + e] : 0.0f;
    }
    if (t < HDIM) s_bias[t] = b_ih[t] + b_hh[t];
    __syncthreads();

    const int h    = t & 63;
    const int rgrp = t >> 6;                   // 0..3
    #pragma unroll
    for (int k = 0; k < 8; k++) {
        int r = rgrp + 4 * k;                  // 0..31
        if (v0 + r >= VOCAB) break;
        float acc = s_bias[h];
        #pragma unroll
        for (int e = 0; e < EDIM; e++)
            acc += s_e[r * EDIM + e] * s_w[h * 65 + e];
        g_proj[(v0 + r) * HDIM + h] = acc;
    }
}

// ---------------------------------------------------------------------------
// Kernel B: TWO rows per warp, SHARED fp32 weights, bf16 h-transport.
// Grid 128 x 128 threads (4 warps) -> at most ONE block per SM: perfectly
// uniform load (fixes R11's 8-vs-4-warp SM imbalance). Each warp owns rows
// rA, rB; lane t owns outputs h[2t], h[2t+1] of BOTH rows using the SAME
// 128 weight regs (dual independent chains = 2x ILP at zero register cost).
// h transported as bf16x2 (8 LDS.128/row/step); expansion is SHF+LOP3
// (4-cyc alu, dual-issues with FFMA2) -- not F2F converts (R12's regression).
// Compute/accum/tanh/xp/fc all fp32. Expected rel_err ~1.3e-4 (gate 1e-3).
// ---------------------------------------------------------------------------
__global__ __launch_bounds__(128, 1) void rnn_bf16_kernel(
    const int*   __restrict__ x32,
    const float* __restrict__ W_hh,
    const float* __restrict__ fc_w,
    const float* __restrict__ fc_b,
    float*       __restrict__ out)
{
    __shared__ int      s_tok[4][2][SEQ];      // 16 KB [warp][row][t]
    __shared__ uint32_t s_h[4][2][2][32];      // 2 KB  [warp][row][buf][lane]

    const int w    = threadIdx.x >> 5;         // warp in block: 0..3
    const int lane = threadIdx.x & 31;
    const int rA   = blockIdx.x * 8 + w * 2;   // this warp's rows
    const int rB   = rA + 1;
    const int flag = g_x64flag;

    // Tokens for both rows (handles int32 or int64 source layout)
    for (int k = lane; k < SEQ; k += 32) {
        long a = (long)rA * SEQ + k;
        long b = (long)rB * SEQ + k;
        s_tok[w][0][k] = flag ? x32[2 * a] : x32[a];
        s_tok[w][1][k] = flag ? x32[2 * b] : x32[b];
    }
    __syncwarp();

    // Shared weights for outputs i0 = 2*lane, i1 = 2*lane+1 (j-pair packed):
    // wp0[l] = (W[i0][2l], W[i0][2l+1]), wp1 likewise. 128 regs, no dup.
    unsigned long long wp0[32], wp1[32];
    {
        const ulonglong2* a = (const ulonglong2*)(W_hh + (2 * lane)     * HDIM);
        const ulonglong2* b = (const ulonglong2*)(W_hh + (2 * lane + 1) * HDIM);
        #pragma unroll
        for (int q = 0; q < 16; q++) {
            ulonglong2 u = a[q]; wp0[2 * q] = u.x; wp0[2 * q + 1] = u.y;
            ulonglong2 v = b[q]; wp1[2 * q] = v.x; wp1[2 * q + 1] = v.y;
        }
    }

    s_h[w][0][0][lane] = 0u;
    s_h[w][1][0][lane] = 0u;
    __syncwarp();

    float hA0 = 0.0f, hA1 = 0.0f, hB0 = 0.0f, hB1 = 0.0f;

    // xp register pipelines, depth 3 per row
    float2 xA0 = *(const float2*)(g_proj + s_tok[w][0][0] * HDIM + 2 * lane);
    float2 xA1 = *(const float2*)(g_proj + s_tok[w][0][1] * HDIM + 2 * lane);
    float2 xA2 = *(const float2*)(g_proj + s_tok[w][0][2] * HDIM + 2 * lane);
    float2 xB0 = *(const float2*)(g_proj + s_tok[w][1][0] * HDIM + 2 * lane);
    float2 xB1 = *(const float2*)(g_proj + s_tok[w][1][1] * HDIM + 2 * lane);
    float2 xB2 = *(const float2*)(g_proj + s_tok[w][1][2] * HDIM + 2 * lane);

    #pragma unroll 2
    for (int t = 0; t < SEQ; t++) {
        const int cur = t & 1, nxt = cur ^ 1;
        const int tp = (t + 3 < SEQ) ? (t + 3) : (SEQ - 1);
        float2 xAf = *(const float2*)(g_proj + s_tok[w][0][tp] * HDIM + 2 * lane);
        float2 xBf = *(const float2*)(g_proj + s_tok[w][1][tp] * HDIM + 2 * lane);

        // 8 accumulators: 2 per output, dual rows (a=rowA, b=rowB)
        unsigned long long a00, a01 = 0ULL, a10, a11 = 0ULL;
        unsigned long long b00, b01 = 0ULL, b10, b11 = 0ULL;
        PACK2F(a00, xA0.x, 0.0f);
        PACK2F(a10, xA0.y, 0.0f);
        PACK2F(b00, xB0.x, 0.0f);
        PACK2F(b10, xB0.y, 0.0f);

        const uint4* hpA = (const uint4*)s_h[w][0][cur];
        const uint4* hpB = (const uint4*)s_h[w][1][cur];
        #pragma unroll
        for (int q = 0; q < 8; q++) {          // uint4 = lanes 4q..4q+3
            uint4 uA = hpA[q];
            uint4 uB = hpB[q];
            #pragma unroll
            for (int k = 0; k < 4; k++) {
                const int l = 4 * q + k;
                uint32_t vA = (&uA.x)[k];
                uint32_t vB = (&uB.x)[k];
                unsigned long long pA = bf16pair_to_f32x2(vA);
                unsigned long long pB = bf16pair_to_f32x2(vB);
                if (k & 1) {
                    FMA2(a01, pA, wp0[l]); FMA2(a11, pA, wp1[l]);
                    FMA2(b01, pB, wp0[l]); FMA2(b11, pB, wp1[l]);
                } else {
                    FMA2(a00, pA, wp0[l]); FMA2(a10, pA, wp1[l]);
                    FMA2(b00, pB, wp0[l]); FMA2(b10, pB, wp1[l]);
                }
            }
        }
        ADD2(a00, a01); ADD2(a10, a11);
        ADD2(b00, b01); ADD2(b10, b11);

        float eA0, oA0, eA1, oA1, eB0, oB0, eB1, oB1;
        UNPACK2(eA0, oA0, a00);
        UNPACK2(eA1, oA1, a10);
        UNPACK2(eB0, oB0, b00);
        UNPACK2(eB1, oB1, b10);
        hA0 = fast_tanh(eA0 + oA0);
        hA1 = fast_tanh(eA1 + oA1);
        hB0 = fast_tanh(eB0 + oB0);
        hB1 = fast_tanh(eB1 + oB1);

        // Publish both pairs as bf16x2 (1 cvt + 1 STS.32 each)
        s_h[w][0][nxt][lane] = f32pair_to_bf16x2(hA0, hA1);
        s_h[w][1][nxt][lane] = f32pair_to_bf16x2(hB0, hB1);
        __syncwarp();

        xA0 = xA1; xA1 = xA2; xA2 = xAf;
        xB0 = xB1; xB1 = xB2; xB2 = xBf;
    }

    // fc + sigmoid for both rows (fp32 register h, warp-local reduce)
    float2 f = *(const float2*)(fc_w + 2 * lane);
    float vA = hA0 * f.x + hA1 * f.y;
    float vB = hB0 * f.x + hB1 * f.y;
    #pragma unroll
    for (int off = 16; off; off >>= 1) {
        vA += __shfl_xor_sync(0xffffffffu, vA, off);
        vB += __shfl_xor_sync(0xffffffffu, vB, off);
    }
    if (lane == 0) {
        float bias = fc_b[0];
        out[rA] = 1.0f / (1.0f + expf(-(vA + bias)));
        out[rB] = 1.0f / (1.0f + expf(-(vB + bias)));
    }
}

// ---------------------------------------------------------------------------
// Launch. Inputs (metadata order): x, emb, W_ih, W_hh, b_ih, b_hh, fc_w, fc_b
// 2 launches/call so ncu -s 5 -c 1 lands on rnn_bf16_kernel.
// ---------------------------------------------------------------------------
extern "C" void kernel_launch(void* const* d_in, const int* in_sizes, int n_in,
                              void* d_out, int out_size)
{
    const int*   x32  = (const int*)  d_in[0];
    const float* emb  = (const float*)d_in[1];
    const float* W_ih = (const float*)d_in[2];
    const float* W_hh = (const float*)d_in[3];
    const float* b_ih = (const float*)d_in[4];
    const float* b_hh = (const float*)d_in[5];
    const float* fc_w = (const float*)d_in[6];
    const float* fc_b = (const float*)d_in[7];
    float* out = (float*)d_out;

    proj_kernel<<<(VOCAB + PROJ_ROWS - 1) / PROJ_ROWS, 256>>>(x32, emb, W_ih, b_ih, b_hh);
    rnn_bf16_kernel<<<BATCH / 8, 128>>>(x32, W_hh, fc_w, fc_b, out);
}

// round 14
// speedup vs baseline: 1.0596x; 1.0596x over previous
#include <cuda_runtime.h>
#include <cuda_bf16.h>
#include <cstdint>

// Problem dims (fixed by the reference)
#define VOCAB 50000
#define EDIM  64
#define HDIM  64
#define BATCH 1024
#define SEQ   512
#define WPB   7            // warps per block (persistent-uniform layout)
#define NBLK  147          // 147*7 = 1029 >= 1024 rows; 1 block per SM

// Scratch: projected table proj[v][h] = b_ih[h]+b_hh[h] + sum_e emb[v,e]*W_ih[h,e]
__device__ float g_proj[VOCAB * HDIM];   // 12.8 MB, L2-resident in steady state
__device__ int   g_x64flag;              // 1 if token buffer is int64, 0 if int32

// Fast tanh: tanh(x) = 1 - 2/(1 + exp(2x)). ex2.approx + rcp.approx.
__device__ __forceinline__ float fast_tanh(float x) {
    float e, r;
    asm("ex2.approx.f32 %0, %1;" : "=f"(e) : "f"(x * 2.885390081777927f)); // 2/ln2
    asm("rcp.approx.f32 %0, %1;" : "=f"(r) : "f"(e + 1.0f));
    return fmaf(-2.0f, r, 1.0f);
}

#define FMA2(acc, a, b) asm("fma.rn.f32x2 %0, %1, %2, %0;" : "+l"(acc) : "l"(a), "l"(b))
#define ADD2(acc, b)    asm("add.rn.f32x2 %0, %0, %1;"     : "+l"(acc) : "l"(b))
#define PACK2F(d, lo, hi) asm("mov.b64 %0, {%1, %2};" : "=l"(d) : "f"(lo), "f"(hi))
#define UNPACK2(lo, hi, s) asm("mov.b64 {%0, %1}, %2;" : "=f"(lo), "=f"(hi) : "l"(s))

// Expand bf16x2 word (h[2l] lo, h[2l+1] hi) into packed f32x2: SHF + LOP3,
// both 4-cyc alu (dual-issues against FFMA2); mov.b64 pairing is free.
__device__ __forceinline__ unsigned long long bf16pair_to_f32x2(uint32_t v) {
    uint32_t lo = v << 16;
    uint32_t hi = v & 0xffff0000u;
    unsigned long long p;
    asm("mov.b64 %0, {%1, %2};" : "=l"(p) : "r"(lo), "r"(hi));
    return p;
}
// Pack two f32 into one bf16x2 word (lo = h0, hi = h1), 1 instr.
__device__ __forceinline__ uint32_t f32pair_to_bf16x2(float h0, float h1) {
    uint32_t u;
    asm("cvt.rn.bf16x2.f32 %0, %1, %2;" : "=r"(u) : "f"(h1), "f"(h0));
    return u;
}

// ---------------------------------------------------------------------------
// Kernel A: build projected embedding table (fuses gather-side GEMM + biases).
// Block 0 warp 0 additionally detects int32-vs-int64 token layout.
// ---------------------------------------------------------------------------
#define PROJ_ROWS 32
__global__ __launch_bounds__(256) void proj_kernel(
    const int*   __restrict__ x32,
    const float* __restrict__ emb,
    const float* __restrict__ W_ih,
    const float* __restrict__ b_ih,
    const float* __restrict__ b_hh)
{
    __shared__ float s_w[HDIM * 65];
    __shared__ float s_e[PROJ_ROWS * EDIM];
    __shared__ float s_bias[HDIM];

    const int t  = threadIdx.x;
    const int v0 = blockIdx.x * PROJ_ROWS;

    if (blockIdx.x == 0 && t < 32) {
        unsigned m = __ballot_sync(0xffffffff, x32[2 * t + 1] != 0);
        if (t == 0) g_x64flag = (m == 0u) ? 1 : 0;
    }

    #pragma unroll
    for (int k = 0; k < 16; k++) {
        int idx = t + k * 256;
        int hg = idx >> 6, eg = idx & 63;
        s_w[hg * 65 + eg] = W_ih[idx];
    }
    #pragma unroll
    for (int k = 0; k < 8; k++) {
        int idx = t + k * 256;
        int r = idx >> 6, e = idx & 63;
        s_e[idx] = (v0 + r < VOCAB) ? emb[(long)(v0 + r) * EDIM + e] : 0.0f;
    }
    if (t < HDIM) s_bias[t] = b_ih[t] + b_hh[t];
    __syncthreads();

    const int h    = t & 63;
    const int rgrp = t >> 6;
    #pragma unroll
    for (int k = 0; k < 8; k++) {
        int r = rgrp + 4 * k;
        if (v0 + r >= VOCAB) break;
        float acc = s_bias[h];
        #pragma unroll
        for (int e = 0; e < EDIM; e++)
            acc += s_e[r * EDIM + e] * s_w[h * 65 + e];
        g_proj[(v0 + r) * HDIM + h] = acc;
    }
}

// ---------------------------------------------------------------------------
// Kernel B: 1 row/warp, bf16 h-transport, uniform 7-warps-per-SM placement.
// 147 blocks x 224 threads; ~180 regs/thread forces exactly 1 block/SM ->
// every SM runs 7 warps (1.75/SMSP): enough TLP to cover each warp's serial
// chain (the R13 failure) while keeping per-step demands balanced:
// MIO 7x32=224, fma/SMSP 224, alu/SMSP 224 cyc.
// Lane t owns h[2t], h[2t+1] (fp32, in regs); transport is bf16x2
// (8 LDS.128/step, SHF+LOP3 expansion -- the cheap path validated in R13).
// Warps fully autonomous: __syncwarp only, no block barriers anywhere.
// ---------------------------------------------------------------------------
__global__ __launch_bounds__(224, 1) void rnn_u7_kernel(
    const int*   __restrict__ x32,
    const float* __restrict__ W_hh,
    const float* __restrict__ fc_w,
    const float* __restrict__ fc_b,
    float*       __restrict__ out)
{
    __shared__ int      s_tok[WPB][SEQ];       // 14 KB [warp][t]
    __shared__ uint32_t s_h[WPB][2][32];       // 1.75 KB [warp][buf][lane]

    const int w    = threadIdx.x >> 5;         // warp in block: 0..6
    const int lane = threadIdx.x & 31;
    const int row  = blockIdx.x * WPB + w;
    const int flag = g_x64flag;

    if (row >= BATCH) return;                  // tail warps idle (no block syncs)

    // Tokens for this warp's row (handles int32 or int64 source layout)
    for (int k = lane; k < SEQ; k += 32) {
        long base = (long)row * SEQ + k;
        s_tok[w][k] = flag ? x32[2 * base] : x32[base];
    }
    __syncwarp();

    // Weights for outputs i0 = 2*lane, i1 = 2*lane+1, j-pair packed:
    // wp0[l] = (W[i0][2l], W[i0][2l+1]), wp1 likewise. 128 regs.
    unsigned long long wp0[32], wp1[32];
    {
        const ulonglong2* a = (const ulonglong2*)(W_hh + (2 * lane)     * HDIM);
        const ulonglong2* b = (const ulonglong2*)(W_hh + (2 * lane + 1) * HDIM);
        #pragma unroll
        for (int q = 0; q < 16; q++) {
            ulonglong2 u = a[q]; wp0[2 * q] = u.x; wp0[2 * q + 1] = u.y;
            ulonglong2 v = b[q]; wp1[2 * q] = v.x; wp1[2 * q + 1] = v.y;
        }
    }

    s_h[w][0][lane] = 0u;                      // bf16x2(0,0)
    __syncwarp();

    float h0 = 0.0f, h1 = 0.0f;

    // xp register pipeline, depth 3 (covers ~3 steps of L2 latency)
    float2 xp0 = *(const float2*)(g_proj + s_tok[w][0] * HDIM + 2 * lane);
    float2 xp1 = *(const float2*)(g_proj + s_tok[w][1] * HDIM + 2 * lane);
    float2 xp2 = *(const float2*)(g_proj + s_tok[w][2] * HDIM + 2 * lane);

    #pragma unroll 2
    for (int t = 0; t < SEQ; t++) {
        const int cur = t & 1, nxt = cur ^ 1;
        const int tp = (t + 3 < SEQ) ? (t + 3) : (SEQ - 1);
        float2 xpf = *(const float2*)(g_proj + s_tok[w][tp] * HDIM + 2 * lane);

        // 8 accumulators (depth-8 chains): a* for output i0, b* for i1
        unsigned long long a0, a1 = 0ULL, a2 = 0ULL, a3 = 0ULL;
        unsigned long long b0, b1 = 0ULL, b2 = 0ULL, b3 = 0ULL;
        PACK2F(a0, xp0.x, 0.0f);
        PACK2F(b0, xp0.y, 0.0f);

        // 8 LDS.128 over the warp's bf16x2 h line (128 B/step)
        const uint4* hp = (const uint4*)s_h[w][cur];
        #pragma unroll
        for (int q = 0; q < 8; q++) {          // uint4 = j-pair words 4q..4q+3
            uint4 u = hp[q];
            unsigned long long p0 = bf16pair_to_f32x2(u.x);
            unsigned long long p1 = bf16pair_to_f32x2(u.y);
            unsigned long long p2 = bf16pair_to_f32x2(u.z);
            unsigned long long p3 = bf16pair_to_f32x2(u.w);
            FMA2(a0, p0, wp0[4 * q + 0]);
            FMA2(a1, p1, wp0[4 * q + 1]);
            FMA2(a2, p2, wp0[4 * q + 2]);
            FMA2(a3, p3, wp0[4 * q + 3]);
            FMA2(b0, p0, wp1[4 * q + 0]);
            FMA2(b1, p1, wp1[4 * q + 1]);
            FMA2(b2, p2, wp1[4 * q + 2]);
            FMA2(b3, p3, wp1[4 * q + 3]);
        }
        ADD2(a0, a1); ADD2(a2, a3); ADD2(a0, a2);
        ADD2(b0, b1); ADD2(b2, b3); ADD2(b0, b2);

        float e0, o0, e1, o1;
        UNPACK2(e0, o0, a0);
        UNPACK2(e1, o1, b0);
        h0 = fast_tanh(e0 + o0);
        h1 = fast_tanh(e1 + o1);

        // Publish own pair as bf16x2 (1 cvt + 1 STS.32)
        s_h[w][nxt][lane] = f32pair_to_bf16x2(h0, h1);
        __syncwarp();

        xp0 = xp1; xp1 = xp2; xp2 = xpf;
    }

    // fc + sigmoid (fp32 register h, warp-local reduce)
    float2 f = *(const float2*)(fc_w + 2 * lane);
    float v = h0 * f.x + h1 * f.y;
    #pragma unroll
    for (int off = 16; off; off >>= 1)
        v += __shfl_xor_sync(0xffffffffu, v, off);
    if (lane == 0)
        out[row] = 1.0f / (1.0f + expf(-(v + fc_b[0])));
}

// ---------------------------------------------------------------------------
// Launch. Inputs (metadata order): x, emb, W_ih, W_hh, b_ih, b_hh, fc_w, fc_b
// 2 launches/call so ncu -s 5 -c 1 lands on rnn_u7_kernel.
// ---------------------------------------------------------------------------
extern "C" void kernel_launch(void* const* d_in, const int* in_sizes, int n_in,
                              void* d_out, int out_size)
{
    const int*   x32  = (const int*)  d_in[0];
    const float* emb  = (const float*)d_in[1];
    const float* W_ih = (const float*)d_in[2];
    const float* W_hh = (const float*)d_in[3];
    const float* b_ih = (const float*)d_in[4];
    const float* b_hh = (const float*)d_in[5];
    const float* fc_w = (const float*)d_in[6];
    const float* fc_b = (const float*)d_in[7];
    float* out = (float*)d_out;

    proj_kernel<<<(VOCAB + PROJ_ROWS - 1) / PROJ_ROWS, 256>>>(x32, emb, W_ih, b_ih, b_hh);
    rnn_u7_kernel<<<NBLK, WPB * 32>>>(x32, W_hh, fc_w, fc_b, out);
}

// round 15
// speedup vs baseline: 1.2500x; 1.1798x over previous
#include <cuda_runtime.h>
#include <cuda_bf16.h>
#include <cstdint>

// Problem dims (fixed by the reference)
#define VOCAB 50000
#define EDIM  64
#define HDIM  64
#define BATCH 1024
#define SEQ   512
#define WPB   7            // warps per block (uniform 1 block/SM)
#define NBLK  147          // 147*7 = 1029 >= 1024 rows

// h line: j in [0,32) at float offset 0; j in [32,64) at offset 36 (16B pad
// shifts banks by 4 -> the two lane-group LDS.128 addresses are conflict-free)
#define HSTR  72           // floats per h buffer (2 halves of 32 + 4 pad)

// Scratch: projected table proj[v][h] = b_ih[h]+b_hh[h] + sum_e emb[v,e]*W_ih[h,e]
__device__ float g_proj[VOCAB * HDIM];   // 12.8 MB, L2-resident in steady state
__device__ int   g_x64flag;              // 1 if token buffer is int64, 0 if int32

// Fast tanh: tanh(x) = 1 - 2/(1 + exp(2x)). ex2.approx + rcp.approx.
__device__ __forceinline__ float fast_tanh(float x) {
    float e, r;
    asm("ex2.approx.f32 %0, %1;" : "=f"(e) : "f"(x * 2.885390081777927f)); // 2/ln2
    asm("rcp.approx.f32 %0, %1;" : "=f"(r) : "f"(e + 1.0f));
    return fmaf(-2.0f, r, 1.0f);
}

#define FMA2(acc, a, b) asm("fma.rn.f32x2 %0, %1, %2, %0;" : "+l"(acc) : "l"(a), "l"(b))
#define ADD2(acc, b)    asm("add.rn.f32x2 %0, %0, %1;"     : "+l"(acc) : "l"(b))
#define PACK2F(d, lo, hi) asm("mov.b64 %0, {%1, %2};" : "=l"(d) : "f"(lo), "f"(hi))
#define UNPACK2(lo, hi, s) asm("mov.b64 {%0, %1}, %2;" : "=f"(lo), "=f"(hi) : "l"(s))

// ---------------------------------------------------------------------------
// Kernel A: build projected embedding table (fuses gather-side GEMM + biases).
// Block 0 warp 0 additionally detects int32-vs-int64 token layout.
// ---------------------------------------------------------------------------
#define PROJ_ROWS 32
__global__ __launch_bounds__(256) void proj_kernel(
    const int*   __restrict__ x32,
    const float* __restrict__ emb,
    const float* __restrict__ W_ih,
    const float* __restrict__ b_ih,
    const float* __restrict__ b_hh)
{
    __shared__ float s_w[HDIM * 65];
    __shared__ float s_e[PROJ_ROWS * EDIM];
    __shared__ float s_bias[HDIM];

    const int t  = threadIdx.x;
    const int v0 = blockIdx.x * PROJ_ROWS;

    if (blockIdx.x == 0 && t < 32) {
        unsigned m = __ballot_sync(0xffffffff, x32[2 * t + 1] != 0);
        if (t == 0) g_x64flag = (m == 0u) ? 1 : 0;
    }

    #pragma unroll
    for (int k = 0; k < 16; k++) {
        int idx = t + k * 256;
        int hg = idx >> 6, eg = idx & 63;
        s_w[hg * 65 + eg] = W_ih[idx];
    }
    #pragma unroll
    for (int k = 0; k < 8; k++) {
        int idx = t + k * 256;
        int r = idx >> 6, e = idx & 63;
        s_e[idx] = (v0 + r < VOCAB) ? emb[(long)(v0 + r) * EDIM + e] : 0.0f;
    }
    if (t < HDIM) s_bias[t] = b_ih[t] + b_hh[t];
    __syncthreads();

    const int h    = t & 63;
    const int rgrp = t >> 6;
    #pragma unroll
    for (int k = 0; k < 8; k++) {
        int r = rgrp + 4 * k;
        if (v0 + r >= VOCAB) break;
        float acc = s_bias[h];
        #pragma unroll
        for (int e = 0; e < EDIM; e++)
            acc += s_e[r * EDIM + e] * s_w[h * 65 + e];
        g_proj[(v0 + r) * HDIM + h] = acc;
    }
}

// ---------------------------------------------------------------------------
// Kernel B: split-j fp32 recurrence. 1 row/warp, 7 warps/block, 147 blocks
// (uniform 1 block/SM). Lane t owns outputs o0=2t, o1=2t+1 AND computes
// partials for partner lane (t^16)'s outputs q0, q1 -- but only over HALF
// the reduction range (t<16 -> j in [0,32), else [32,64)). This halves the
// broadcast LDS work (8 LDS.128 vs 16) at the SAME 128 weight registers and
// the SAME 64 FFMA2; one shfl_xor(16) per output merges the two halves.
// Pure fp32 everywhere (no bf16 expansions -- R14's 64-alu/step tax is gone).
// ---------------------------------------------------------------------------
__global__ __launch_bounds__(224, 1) void rnn_split_kernel(
    const int*   __restrict__ x32,
    const float* __restrict__ W_hh,
    const float* __restrict__ fc_w,
    const float* __restrict__ fc_b,
    float*       __restrict__ out)
{
    __shared__ int   s_tok[WPB][SEQ];          // 14 KB [warp][t]
    __shared__ float s_h[WPB][2][HSTR];        // ~4 KB [warp][buf][padded h]

    const int w    = threadIdx.x >> 5;         // warp in block: 0..6
    const int lane = threadIdx.x & 31;
    const int row  = blockIdx.x * WPB + w;
    const int flag = g_x64flag;

    if (row >= BATCH) return;                  // tail warps idle (warp-local syncs only)

    const int  lo    = (lane < 16);            // my j-half: [0,32) or [32,64)
    const int  jbase = lo ? 0 : 32;            // j offset of my half
    const int  hoff  = lo ? 0 : 36;            // float offset of my half (16B pad)
    const int  part  = lane ^ 16;              // partner lane
    const int  o0 = 2 * lane;                  // my outputs
    const int  q0 = 2 * part;                  // partner's outputs

    // Tokens for this warp's row (handles int32 or int64 source layout)
    for (int k = lane; k < SEQ; k += 32) {
        long base = (long)row * SEQ + k;
        s_tok[w][k] = flag ? x32[2 * base] : x32[base];
    }
    __syncwarp();

    // Weights: 4 output-rows x my j-half, j-pair packed = 64 packed regs.
    // wA/wB -> my outputs o0, o1; wC/wD -> partner outputs q0, q1.
    unsigned long long wA[16], wB[16], wC[16], wD[16];
    {
        const ulonglong2* pa = (const ulonglong2*)(W_hh + (o0)     * HDIM + jbase);
        const ulonglong2* pb = (const ulonglong2*)(W_hh + (o0 + 1) * HDIM + jbase);
        const ulonglong2* pc = (const ulonglong2*)(W_hh + (q0)     * HDIM + jbase);
        const ulonglong2* pd = (const ulonglong2*)(W_hh + (q0 + 1) * HDIM + jbase);
        #pragma unroll
        for (int q = 0; q < 8; q++) {
            ulonglong2 a = pa[q]; wA[2 * q] = a.x; wA[2 * q + 1] = a.y;
            ulonglong2 b = pb[q]; wB[2 * q] = b.x; wB[2 * q + 1] = b.y;
            ulonglong2 c = pc[q]; wC[2 * q] = c.x; wC[2 * q + 1] = c.y;
            ulonglong2 d = pd[q]; wD[2 * q] = d.x; wD[2 * q + 1] = d.y;
        }
    }

    // h init: lane writes its own pair into buffer 0 (pads never read)
    *(float2*)&s_h[w][0][2 * lane + (lo ? 0 : 4)] = make_float2(0.0f, 0.0f);
    __syncwarp();

    float h0 = 0.0f, h1 = 0.0f;

    // xp register pipeline, depth 3 (covers ~3 steps of L2 latency)
    float2 xp0 = *(const float2*)(g_proj + s_tok[w][0] * HDIM + o0);
    float2 xp1 = *(const float2*)(g_proj + s_tok[w][1] * HDIM + o0);
    float2 xp2 = *(const float2*)(g_proj + s_tok[w][2] * HDIM + o0);

    #pragma unroll 2
    for (int t = 0; t < SEQ; t++) {
        const int cur = t & 1, nxt = cur ^ 1;
        const int tp = (t + 3 < SEQ) ? (t + 3) : (SEQ - 1);
        float2 xpf = *(const float2*)(g_proj + s_tok[w][tp] * HDIM + o0);

        // 8 accumulators, chain depth 8: (aX0,aX1) per output row
        unsigned long long aA0 = 0, aA1 = 0, aB0 = 0, aB1 = 0;
        unsigned long long aC0 = 0, aC1 = 0, aD0 = 0, aD1 = 0;

        // 8 LDS.128 over my j-half (two conflict-free address groups)
        const float4* hp = (const float4*)&s_h[w][cur][hoff];
        #pragma unroll
        for (int q = 0; q < 8; q++) {          // float4 = j-pairs 2q, 2q+1
            float4 u = hp[q];
            unsigned long long p0, p1;
            PACK2F(p0, u.x, u.y);
            PACK2F(p1, u.z, u.w);
            FMA2(aA0, p0, wA[2 * q]); FMA2(aA1, p1, wA[2 * q + 1]);
            FMA2(aB0, p0, wB[2 * q]); FMA2(aB1, p1, wB[2 * q + 1]);
            FMA2(aC0, p0, wC[2 * q]); FMA2(aC1, p1, wC[2 * q + 1]);
            FMA2(aD0, p0, wD[2 * q]); FMA2(aD1, p1, wD[2 * q + 1]);
        }
        ADD2(aA0, aA1); ADD2(aB0, aB1); ADD2(aC0, aC1); ADD2(aD0, aD1);

        float eA, oA, eB, oB, eC, oC, eD, oD;
        UNPACK2(eA, oA, aA0); UNPACK2(eB, oB, aB0);
        UNPACK2(eC, oC, aC0); UNPACK2(eD, oD, aD0);
        float sO0 = eA + oA;                   // my outputs, my half
        float sO1 = eB + oB;
        float sQ0 = eC + oC;                   // partner outputs, my half
        float sQ1 = eD + oD;

        // Merge halves: partner's sQ* are MY outputs' other-half partials
        float r0 = __shfl_xor_sync(0xffffffffu, sQ0, 16);
        float r1 = __shfl_xor_sync(0xffffffffu, sQ1, 16);

        h0 = fast_tanh(xp0.x + sO0 + r0);
        h1 = fast_tanh(xp0.y + sO1 + r1);

        // Publish own pair (STS.64), warp-local sync only
        *(float2*)&s_h[w][nxt][2 * lane + (lo ? 0 : 4)] = make_float2(h0, h1);
        __syncwarp();

        xp0 = xp1; xp1 = xp2; xp2 = xpf;
    }

    // fc + sigmoid (fp32 register h, warp-local reduce)
    float2 f = *(const float2*)(fc_w + o0);
    float v = h0 * f.x + h1 * f.y;
    #pragma unroll
    for (int off = 16; off; off >>= 1)
        v += __shfl_xor_sync(0xffffffffu, v, off);
    if (lane == 0)
        out[row] = 1.0f / (1.0f + expf(-(v + fc_b[0])));
}

// ---------------------------------------------------------------------------
// Launch. Inputs (metadata order): x, emb, W_ih, W_hh, b_ih, b_hh, fc_w, fc_b
// 2 launches/call so ncu -s 5 -c 1 lands on rnn_split_kernel.
// ---------------------------------------------------------------------------
extern "C" void kernel_launch(void* const* d_in, const int* in_sizes, int n_in,
                              void* d_out, int out_size)
{
    const int*   x32  = (const int*)  d_in[0];
    const float* emb  = (const float*)d_in[1];
    const float* W_ih = (const float*)d_in[2];
    const float* W_hh = (const float*)d_in[3];
    const float* b_ih = (const float*)d_in[4];
    const float* b_hh = (const float*)d_in[5];
    const float* fc_w = (const float*)d_in[6];
    const float* fc_b = (const float*)d_in[7];
    float* out = (float*)d_out;

    proj_kernel<<<(VOCAB + PROJ_ROWS - 1) / PROJ_ROWS, 256>>>(x32, emb, W_ih, b_ih, b_hh);
    rnn_split_kernel<<<NBLK, WPB * 32>>>(x32, W_hh, fc_w, fc_b, out);
}